// round 1
// baseline (speedup 1.0000x reference)
#include <cuda_runtime.h>

#define Bv 8192
#define Tv 512
#define NTv 7

__device__ float g_partial[Bv];

__global__ void __launch_bounds__(32)
crf_fwd_kernel(const float* __restrict__ em,
               const int* __restrict__ labels,
               const int* __restrict__ mask,
               const float* __restrict__ startT,
               const float* __restrict__ endT,
               const float* __restrict__ trans)
{
    __shared__ float sTrans[NTv * NTv];
    const int tid = threadIdx.x;
    for (int i = tid; i < NTv * NTv; i += 32) sTrans[i] = trans[i];
    __syncthreads();

    const int b = blockIdx.x * 32 + tid;
    const float* eb = em + (size_t)b * (Tv * NTv);
    const int4* lb4 = (const int4*)(labels + (size_t)b * Tv);
    const int4* mb4 = (const int4*)(mask + (size_t)b * Tv);

    // Precompute exp(transitions) into registers (constant indices -> no spills)
    float E[NTv][NTv];
#pragma unroll
    for (int i = 0; i < NTv; i++)
#pragma unroll
        for (int j = 0; j < NTv; j++)
            E[i][j] = __expf(__ldg(&trans[i * NTv + j]));

    float p[NTv];      // current forward distribution (max normalized to [1,2))
    int xsum = 0;      // accumulated base-2 exponent of the normalization
    float num;         // numerator (gold path score)
    int prev;          // previous tag

    float bufA[28], bufB[28];
    int4 lA, lB, mA, mB;

#define LOADE(BUF, MM) do { \
    const float4* _p4 = (const float4*)(eb + (MM) * 28); \
    _Pragma("unroll") \
    for (int k = 0; k < 7; k++) { \
        float4 _v = __ldg(_p4 + k); \
        BUF[4*k+0]=_v.x; BUF[4*k+1]=_v.y; BUF[4*k+2]=_v.z; BUF[4*k+3]=_v.w; \
    } } while (0)

    LOADE(bufA, 0);
    lA = __ldg(lb4 + 0); mA = __ldg(mb4 + 0);
    LOADE(bufB, 1);
    lB = __ldg(lb4 + 1); mB = __ldg(mb4 + 1);

    auto STEP = [&](float e0, float e1, float e2, float e3, float e4, float e5, float e6,
                    int L, int M, int t) {
        if (L < 0) L = 0;
        float x[7];
        x[0] = __expf(e0); x[1] = __expf(e1); x[2] = __expf(e2); x[3] = __expf(e3);
        x[4] = __expf(e4); x[5] = __expf(e5); x[6] = __expf(e6);
        float q[7];
#pragma unroll
        for (int j = 0; j < 7; j++) q[j] = p[0] * E[0][j];
#pragma unroll
        for (int i = 1; i < 7; i++)
#pragma unroll
            for (int j = 0; j < 7; j++) q[j] = fmaf(p[i], E[i][j], q[j]);
#pragma unroll
        for (int j = 0; j < 7; j++) q[j] *= x[j];
        if (M) {
            float mx = q[0];
#pragma unroll
            for (int j = 1; j < 7; j++) mx = fmaxf(mx, q[j]);
            int ex = (__float_as_int(mx) >> 23) & 0xFF;       // biased exponent
            float inv = __int_as_float((254 - ex) << 23);     // exact 2^(127-(ex-127))
            xsum += ex - 127;
#pragma unroll
            for (int j = 0; j < 7; j++) p[j] = q[j] * inv;
            // numerator: trans[prev, L] + emissions[b, t, L]
            float eL = __ldg(eb + t * 7 + L);                 // L1-resident line
            num += sTrans[prev * 7 + L] + eL;
            prev = L;
        }
    };

    // ---- step 0 (init): score = start + emissions[:,0], always counted ----
    {
        float q[7];
#pragma unroll
        for (int j = 0; j < 7; j++) q[j] = __expf(__ldg(startT + j) + bufA[j]);
        float mx = q[0];
#pragma unroll
        for (int j = 1; j < 7; j++) mx = fmaxf(mx, q[j]);
        int ex = (__float_as_int(mx) >> 23) & 0xFF;
        float inv = __int_as_float((254 - ex) << 23);
        xsum = ex - 127;
#pragma unroll
        for (int j = 0; j < 7; j++) p[j] = q[j] * inv;
        int L0 = lA.x; if (L0 < 0) L0 = 0;
        num = __ldg(startT + L0) + __ldg(eb + L0);
        prev = L0;
    }

#define PROC4_TAIL3(BUF, L4, M4, TB) do { \
    STEP(BUF[7],BUF[8],BUF[9],BUF[10],BUF[11],BUF[12],BUF[13],  (L4).y,(M4).y,(TB)+1); \
    STEP(BUF[14],BUF[15],BUF[16],BUF[17],BUF[18],BUF[19],BUF[20],(L4).z,(M4).z,(TB)+2); \
    STEP(BUF[21],BUF[22],BUF[23],BUF[24],BUF[25],BUF[26],BUF[27],(L4).w,(M4).w,(TB)+3); } while(0)

#define PROC4(BUF, L4, M4, TB) do { \
    STEP(BUF[0],BUF[1],BUF[2],BUF[3],BUF[4],BUF[5],BUF[6],      (L4).x,(M4).x,(TB)+0); \
    PROC4_TAIL3(BUF, L4, M4, TB); } while(0)

    // steps 1..3 from macro-block 0
    PROC4_TAIL3(bufA, lA, mA, 0);

    // double-buffered mainloop: process macro m while macro m+1 loads are in flight
#pragma unroll 1
    for (int m = 2; m < 128; m += 2) {
        LOADE(bufA, m);
        lA = __ldg(lb4 + m); mA = __ldg(mb4 + m);
        PROC4(bufB, lB, mB, (m - 1) * 4);
        if (m + 1 < 128) {
            LOADE(bufB, m + 1);
            lB = __ldg(lb4 + m + 1); mB = __ldg(mb4 + m + 1);
        }
        PROC4(bufA, lA, mA, m * 4);
    }
    PROC4(bufB, lB, mB, 127 * 4);   // macro 127 (steps 508..511)

    // ---- finish: den = log(sum_j p[j]*exp(end[j])) + xsum*ln2 ; num += end[last] ----
    float acc = 0.f;
#pragma unroll
    for (int j = 0; j < 7; j++) acc = fmaf(p[j], __expf(__ldg(endT + j)), acc);
    float den = __logf(acc) + (float)xsum * 0.69314718055994531f;
    float numf = num + __ldg(endT + prev);
    g_partial[b] = den - numf;

#undef LOADE
#undef PROC4
#undef PROC4_TAIL3
}

__global__ void reduce_kernel(float* __restrict__ out)
{
    __shared__ float s[256];
    float acc = 0.f;
    for (int i = threadIdx.x; i < Bv; i += 256) acc += g_partial[i];
    s[threadIdx.x] = acc;
    __syncthreads();
#pragma unroll
    for (int off = 128; off > 0; off >>= 1) {
        if (threadIdx.x < off) s[threadIdx.x] += s[threadIdx.x + off];
        __syncthreads();
    }
    if (threadIdx.x == 0) out[0] = s[0];
}

extern "C" void kernel_launch(void* const* d_in, const int* in_sizes, int n_in,
                              void* d_out, int out_size)
{
    const float* em     = (const float*)d_in[0];
    const int*   labels = (const int*)  d_in[1];
    const int*   mask   = (const int*)  d_in[2];
    const float* startT = (const float*)d_in[3];
    const float* endT   = (const float*)d_in[4];
    const float* trans  = (const float*)d_in[5];

    crf_fwd_kernel<<<Bv / 32, 32>>>(em, labels, mask, startT, endT, trans);
    reduce_kernel<<<1, 256>>>((float*)d_out);
}

// round 2
// speedup vs baseline: 1.0500x; 1.0500x over previous
#include <cuda_runtime.h>

#define Bv 8192
#define Tv 512
#define NTv 7

typedef unsigned long long u64;

__device__ __forceinline__ u64 PK(float a, float b) {
    u64 r;
    asm("mov.b64 %0, {%1, %2};" : "=l"(r) : "r"(__float_as_uint(a)), "r"(__float_as_uint(b)));
    return r;
}
__device__ __forceinline__ void UPK(u64 v, float& a, float& b) {
    unsigned x, y;
    asm("mov.b64 {%0, %1}, %2;" : "=r"(x), "=r"(y) : "l"(v));
    a = __uint_as_float(x); b = __uint_as_float(y);
}
__device__ __forceinline__ u64 FMA2(u64 a, u64 b, u64 c) {
    u64 d;
    asm("fma.rn.f32x2 %0, %1, %2, %3;" : "=l"(d) : "l"(a), "l"(b), "l"(c));
    return d;
}
__device__ __forceinline__ u64 MUL2(u64 a, u64 b) {
    u64 d;
    asm("mul.rn.f32x2 %0, %1, %2;" : "=l"(d) : "l"(a), "l"(b));
    return d;
}

__global__ void __launch_bounds__(32)
crf_fwd_kernel(const float* __restrict__ em,
               const int* __restrict__ labels,
               const int* __restrict__ mask,
               const float* __restrict__ startT,
               const float* __restrict__ endT,
               const float* __restrict__ trans,
               float* __restrict__ out)
{
    __shared__ float sTrans[NTv * NTv];
    const int tid = threadIdx.x;
    for (int i = tid; i < NTv * NTv; i += 32) sTrans[i] = trans[i];
    __syncthreads();

    const int b = blockIdx.x * 32 + tid;
    const float* eb = em + (size_t)b * (Tv * NTv);
    const int4* lb4 = (const int4*)(labels + (size_t)b * Tv);
    const int4* mb4 = (const int4*)(mask + (size_t)b * Tv);

    // exp(transitions), packed as f32x2 column pairs + scalar col 6
    u64 EP[NTv][3];
    float E6[NTv];
#pragma unroll
    for (int i = 0; i < NTv; i++) {
        float e0 = __expf(__ldg(&trans[i * 7 + 0]));
        float e1 = __expf(__ldg(&trans[i * 7 + 1]));
        float e2 = __expf(__ldg(&trans[i * 7 + 2]));
        float e3 = __expf(__ldg(&trans[i * 7 + 3]));
        float e4 = __expf(__ldg(&trans[i * 7 + 4]));
        float e5 = __expf(__ldg(&trans[i * 7 + 5]));
        EP[i][0] = PK(e0, e1); EP[i][1] = PK(e2, e3); EP[i][2] = PK(e4, e5);
        E6[i] = __expf(__ldg(&trans[i * 7 + 6]));
    }

    u64 p01, p23, p45;   // forward distribution, packed pairs
    float p6;
    int xsum = 0;        // accumulated base-2 exponent
    float num;           // gold-path score
    int prev;            // previous (clamped) tag

    float bufA[56], bufB[56];
    int4 lA0, lA1, lB0, lB1, mA0, mA1, mB0, mB1;

#define LOAD8(BUF, MM) do { \
    const float4* _p4 = (const float4*)(eb + (MM) * 56); \
    _Pragma("unroll") \
    for (int k = 0; k < 14; k++) { \
        float4 _v = __ldg(_p4 + k); \
        BUF[4*k+0]=_v.x; BUF[4*k+1]=_v.y; BUF[4*k+2]=_v.z; BUF[4*k+3]=_v.w; \
    } } while (0)

#define EXPALL(BUF) do { \
    _Pragma("unroll") \
    for (int k = 0; k < 56; k++) BUF[k] = __expf(BUF[k]); } while (0)

    // one recursion step; x0..x6 = exp(emissions[t])
    auto STEP = [&](float x0, float x1, float x2, float x3, float x4, float x5, float x6,
                    int L, int M, int t) {
        float a0, a1, a2, a3, a4, a5;
        UPK(p01, a0, a1); UPK(p23, a2, a3); UPK(p45, a4, a5);
        u64 bb, q01, q23, q45; float q6;
        bb = PK(a0, a0);
        q01 = MUL2(bb, EP[0][0]); q23 = MUL2(bb, EP[0][1]); q45 = MUL2(bb, EP[0][2]);
        q6 = a0 * E6[0];
        bb = PK(a1, a1);
        q01 = FMA2(bb, EP[1][0], q01); q23 = FMA2(bb, EP[1][1], q23); q45 = FMA2(bb, EP[1][2], q45);
        q6 = fmaf(a1, E6[1], q6);
        bb = PK(a2, a2);
        q01 = FMA2(bb, EP[2][0], q01); q23 = FMA2(bb, EP[2][1], q23); q45 = FMA2(bb, EP[2][2], q45);
        q6 = fmaf(a2, E6[2], q6);
        bb = PK(a3, a3);
        q01 = FMA2(bb, EP[3][0], q01); q23 = FMA2(bb, EP[3][1], q23); q45 = FMA2(bb, EP[3][2], q45);
        q6 = fmaf(a3, E6[3], q6);
        bb = PK(a4, a4);
        q01 = FMA2(bb, EP[4][0], q01); q23 = FMA2(bb, EP[4][1], q23); q45 = FMA2(bb, EP[4][2], q45);
        q6 = fmaf(a4, E6[4], q6);
        bb = PK(a5, a5);
        q01 = FMA2(bb, EP[5][0], q01); q23 = FMA2(bb, EP[5][1], q23); q45 = FMA2(bb, EP[5][2], q45);
        q6 = fmaf(a5, E6[5], q6);
        bb = PK(p6, p6);
        q01 = FMA2(bb, EP[6][0], q01); q23 = FMA2(bb, EP[6][1], q23); q45 = FMA2(bb, EP[6][2], q45);
        q6 = fmaf(p6, E6[6], q6);
        // multiply by exp(emissions)
        q01 = MUL2(q01, PK(x0, x1));
        q23 = MUL2(q23, PK(x2, x3));
        q45 = MUL2(q45, PK(x4, x5));
        q6 *= x6;
        // mask select (no branch)
        p01 = M ? q01 : p01;
        p23 = M ? q23 : p23;
        p45 = M ? q45 : p45;
        p6  = M ? q6  : p6;
        // numerator (off critical path)
        int Lc = L < 0 ? 0 : L;
        float eL = __ldg(eb + t * 7 + Lc);
        float v = sTrans[prev * 7 + Lc] + eL;
        num += M ? v : 0.0f;
        prev = M ? Lc : prev;
    };

#define RENORM() do { \
    float a0,a1,a2,a3,a4,a5; \
    UPK(p01,a0,a1); UPK(p23,a2,a3); UPK(p45,a4,a5); \
    float mx = fmaxf(fmaxf(fmaxf(a0,a1), fmaxf(a2,a3)), fmaxf(fmaxf(a4,a5), p6)); \
    int ex = (__float_as_int(mx) >> 23) & 0xFF; \
    float inv = __int_as_float((254 - ex) << 23); \
    xsum += ex - 127; \
    u64 iv = PK(inv, inv); \
    p01 = MUL2(p01, iv); p23 = MUL2(p23, iv); p45 = MUL2(p45, iv); p6 *= inv; } while (0)

#define STEP7(BUF, S, L, M, T) \
    STEP(BUF[(S)*7+0],BUF[(S)*7+1],BUF[(S)*7+2],BUF[(S)*7+3],BUF[(S)*7+4],BUF[(S)*7+5],BUF[(S)*7+6],(L),(M),(T))

#define PROC8(BUF, LA, LB, MA, MB, TB) do { \
    EXPALL(BUF); \
    STEP7(BUF,0,(LA).x,(MA).x,(TB)+0); STEP7(BUF,1,(LA).y,(MA).y,(TB)+1); \
    STEP7(BUF,2,(LA).z,(MA).z,(TB)+2); STEP7(BUF,3,(LA).w,(MA).w,(TB)+3); \
    STEP7(BUF,4,(LB).x,(MB).x,(TB)+4); STEP7(BUF,5,(LB).y,(MB).y,(TB)+5); \
    STEP7(BUF,6,(LB).z,(MB).z,(TB)+6); STEP7(BUF,7,(LB).w,(MB).w,(TB)+7); \
    RENORM(); } while (0)

    // preload macros 0 and 1
    LOAD8(bufA, 0); lA0 = __ldg(lb4 + 0); lA1 = __ldg(lb4 + 1);
    mA0 = __ldg(mb4 + 0); mA1 = __ldg(mb4 + 1);
    LOAD8(bufB, 1); lB0 = __ldg(lb4 + 2); lB1 = __ldg(lb4 + 3);
    mB0 = __ldg(mb4 + 2); mB1 = __ldg(mb4 + 3);

    // ---- init (t=0): p = normalize(exp(start + emissions[0])), always counted ----
    {
        float q[7];
#pragma unroll
        for (int j = 0; j < 7; j++) q[j] = __expf(__ldg(startT + j) + bufA[j]);
        float mx = q[0];
#pragma unroll
        for (int j = 1; j < 7; j++) mx = fmaxf(mx, q[j]);
        int ex = (__float_as_int(mx) >> 23) & 0xFF;
        float inv = __int_as_float((254 - ex) << 23);
        xsum = ex - 127;
        p01 = PK(q[0]*inv, q[1]*inv);
        p23 = PK(q[2]*inv, q[3]*inv);
        p45 = PK(q[4]*inv, q[5]*inv);
        p6  = q[6]*inv;
        int L0 = lA0.x < 0 ? 0 : lA0.x;
        num = __ldg(startT + L0) + __ldg(eb + L0);
        prev = L0;
    }

    // ---- macro 0: steps 1..7 ----
    EXPALL(bufA);
    STEP7(bufA,1,lA0.y,mA0.y,1); STEP7(bufA,2,lA0.z,mA0.z,2); STEP7(bufA,3,lA0.w,mA0.w,3);
    STEP7(bufA,4,lA1.x,mA1.x,4); STEP7(bufA,5,lA1.y,mA1.y,5);
    STEP7(bufA,6,lA1.z,mA1.z,6); STEP7(bufA,7,lA1.w,mA1.w,7);
    RENORM();

    // ---- mainloop: macros 2..63, double buffered, one-macro prefetch distance ----
#pragma unroll 1
    for (int m = 2; m < 64; m += 2) {
        LOAD8(bufA, m);
        lA0 = __ldg(lb4 + 2*m); lA1 = __ldg(lb4 + 2*m + 1);
        mA0 = __ldg(mb4 + 2*m); mA1 = __ldg(mb4 + 2*m + 1);
        PROC8(bufB, lB0, lB1, mB0, mB1, (m - 1) * 8);
        LOAD8(bufB, m + 1);
        lB0 = __ldg(lb4 + 2*m + 2); lB1 = __ldg(lb4 + 2*m + 3);
        mB0 = __ldg(mb4 + 2*m + 2); mB1 = __ldg(mb4 + 2*m + 3);
        PROC8(bufA, lA0, lA1, mA0, mA1, m * 8);
    }
    PROC8(bufB, lB0, lB1, mB0, mB1, 63 * 8);

    // ---- finish ----
    float a0,a1,a2,a3,a4,a5;
    UPK(p01,a0,a1); UPK(p23,a2,a3); UPK(p45,a4,a5);
    float acc = a0 * __expf(__ldg(endT + 0));
    acc = fmaf(a1, __expf(__ldg(endT + 1)), acc);
    acc = fmaf(a2, __expf(__ldg(endT + 2)), acc);
    acc = fmaf(a3, __expf(__ldg(endT + 3)), acc);
    acc = fmaf(a4, __expf(__ldg(endT + 4)), acc);
    acc = fmaf(a5, __expf(__ldg(endT + 5)), acc);
    acc = fmaf(p6, __expf(__ldg(endT + 6)), acc);
    float den = __logf(acc) + (float)xsum * 0.69314718055994531f;
    float numf = num + __ldg(endT + prev);
    float r = den - numf;

    // warp reduce + single atomic per CTA
#pragma unroll
    for (int off = 16; off > 0; off >>= 1)
        r += __shfl_xor_sync(0xFFFFFFFFu, r, off);
    if (tid == 0) atomicAdd(out, r);

#undef LOAD8
#undef EXPALL
#undef RENORM
#undef STEP7
#undef PROC8
}

extern "C" void kernel_launch(void* const* d_in, const int* in_sizes, int n_in,
                              void* d_out, int out_size)
{
    const float* em     = (const float*)d_in[0];
    const int*   labels = (const int*)  d_in[1];
    const int*   mask   = (const int*)  d_in[2];
    const float* startT = (const float*)d_in[3];
    const float* endT   = (const float*)d_in[4];
    const float* trans  = (const float*)d_in[5];

    cudaMemsetAsync(d_out, 0, sizeof(float));
    crf_fwd_kernel<<<Bv / 32, 32>>>(em, labels, mask, startT, endT, trans, (float*)d_out);
}

// round 3
// speedup vs baseline: 1.5634x; 1.4889x over previous
#include <cuda_runtime.h>

#define Bv 8192
#define Tv 512

typedef unsigned long long u64;

__device__ __forceinline__ u64 PK(float a, float b) {
    u64 r; asm("mov.b64 %0,{%1,%2};" : "=l"(r) : "r"(__float_as_uint(a)), "r"(__float_as_uint(b))); return r;
}
__device__ __forceinline__ void UPK(u64 v, float& a, float& b) {
    unsigned x, y; asm("mov.b64 {%0,%1},%2;" : "=r"(x), "=r"(y) : "l"(v));
    a = __uint_as_float(x); b = __uint_as_float(y);
}
__device__ __forceinline__ u64 FMA2(u64 a, u64 b, u64 c) {
    u64 d; asm("fma.rn.f32x2 %0,%1,%2,%3;" : "=l"(d) : "l"(a), "l"(b), "l"(c)); return d;
}
__device__ __forceinline__ u64 MUL2(u64 a, u64 b) {
    u64 d; asm("mul.rn.f32x2 %0,%1,%2;" : "=l"(d) : "l"(a), "l"(b)); return d;
}
__device__ __forceinline__ void cpa16(float* dst, const void* src) {
    unsigned d = (unsigned)__cvta_generic_to_shared(dst);
    asm volatile("cp.async.cg.shared.global [%0], [%1], 16;" :: "r"(d), "l"(src));
}
#define CP_COMMIT() asm volatile("cp.async.commit_group;")
#define CP_WAIT2()  asm volatile("cp.async.wait_group 2;")

// smem layout: per warp, 3 stages, 32 rows, 60 floats/row (56 data + 4 pad; 240B row
// stride keeps 16B alignment for cp.async; 4-way LDS bank conflict is tolerable)
#define ROWW 60

__global__ void __launch_bounds__(64, 1)
crf_fwd_kernel(const float* __restrict__ em,
               const int* __restrict__ labels,
               const int* __restrict__ mask,
               const float* __restrict__ startT,
               const float* __restrict__ endT,
               const float* __restrict__ trans,
               float* __restrict__ out)
{
    __shared__ float sm[2][3][32 * ROWW];
    __shared__ float sTrans[49];

    const int tid  = threadIdx.x;
    const int wid  = tid >> 5;
    const int lane = tid & 31;

    for (int i = tid; i < 49; i += 64) sTrans[i] = trans[i];
    __syncthreads();

    const int b = blockIdx.x * 64 + tid;
    // warp-base emission pointer (row = lane)
    const float* ebw = em + (size_t)(blockIdx.x * 64 + wid * 32) * (Tv * 7);
    const int4* lb4 = (const int4*)(labels + (size_t)b * Tv);
    const int4* mb4 = (const int4*)(mask + (size_t)b * Tv);

    // exp(transitions) in registers: packed pairs for cols 0-5, scalar col 6
    u64 EP[7][3]; float E6[7];
#pragma unroll
    for (int i = 0; i < 7; i++) {
        float e0 = __expf(__ldg(&trans[i*7+0])), e1 = __expf(__ldg(&trans[i*7+1]));
        float e2 = __expf(__ldg(&trans[i*7+2])), e3 = __expf(__ldg(&trans[i*7+3]));
        float e4 = __expf(__ldg(&trans[i*7+4])), e5 = __expf(__ldg(&trans[i*7+5]));
        EP[i][0] = PK(e0,e1); EP[i][1] = PK(e2,e3); EP[i][2] = PK(e4,e5);
        E6[i] = __expf(__ldg(&trans[i*7+6]));
    }

    // stage macro MM (8 steps, 224B/row) into stage MM%3, coalesced across lanes
#define STAGE(MM) do { \
    float* _base = &sm[wid][(MM) % 3][0]; \
    const float* _g = ebw + (MM) * 56; \
    _Pragma("unroll") \
    for (int i = 0; i < 14; i++) { \
        int idx = i * 32 + lane; \
        int r = (idx * 4682) >> 16;     /* exact /14 for idx<448 */ \
        int c = idx - r * 14; \
        cpa16(_base + r * ROWW + c * 4, _g + (size_t)r * (Tv*7) + c * 4); \
    } \
    CP_COMMIT(); } while (0)

    u64 p01, p23, p45; float p6;
    int xsum = 0;
    float num;
    int prev;

    const float* myrow0 = &sm[wid][0][lane * ROWW];
    const float* myrow1 = &sm[wid][1][lane * ROWW];
    const float* myrow2 = &sm[wid][2][lane * ROWW];

    // one recursion step; raw emissions read from rowp[s*7 + k]
    auto STEP = [&](const float* rowp, int s, int L, int M) {
        const float* ep = rowp + s * 7;
        int Lc = L < 0 ? 0 : L;
        float r0=ep[0], r1=ep[1], r2=ep[2], r3=ep[3], r4=ep[4], r5=ep[5], r6=ep[6];
        float rawL = ep[Lc];
        // numerator (off critical path)
        float v = sTrans[prev * 7 + Lc] + rawL;
        num += M ? v : 0.0f;
        prev = M ? Lc : prev;
        // exp of emissions
        float x0=__expf(r0), x1=__expf(r1), x2=__expf(r2), x3=__expf(r3);
        float x4=__expf(r4), x5=__expf(r5), x6=__expf(r6);
        // 7x7 matvec in packed pairs
        float a0,a1,a2,a3,a4,a5;
        UPK(p01,a0,a1); UPK(p23,a2,a3); UPK(p45,a4,a5);
        u64 bb, q01, q23, q45; float q6;
        bb = PK(a0,a0);
        q01 = MUL2(bb,EP[0][0]); q23 = MUL2(bb,EP[0][1]); q45 = MUL2(bb,EP[0][2]);
        q6 = a0 * E6[0];
        bb = PK(a1,a1);
        q01 = FMA2(bb,EP[1][0],q01); q23 = FMA2(bb,EP[1][1],q23); q45 = FMA2(bb,EP[1][2],q45);
        q6 = fmaf(a1,E6[1],q6);
        bb = PK(a2,a2);
        q01 = FMA2(bb,EP[2][0],q01); q23 = FMA2(bb,EP[2][1],q23); q45 = FMA2(bb,EP[2][2],q45);
        q6 = fmaf(a2,E6[2],q6);
        bb = PK(a3,a3);
        q01 = FMA2(bb,EP[3][0],q01); q23 = FMA2(bb,EP[3][1],q23); q45 = FMA2(bb,EP[3][2],q45);
        q6 = fmaf(a3,E6[3],q6);
        bb = PK(a4,a4);
        q01 = FMA2(bb,EP[4][0],q01); q23 = FMA2(bb,EP[4][1],q23); q45 = FMA2(bb,EP[4][2],q45);
        q6 = fmaf(a4,E6[4],q6);
        bb = PK(a5,a5);
        q01 = FMA2(bb,EP[5][0],q01); q23 = FMA2(bb,EP[5][1],q23); q45 = FMA2(bb,EP[5][2],q45);
        q6 = fmaf(a5,E6[5],q6);
        bb = PK(p6,p6);
        q01 = FMA2(bb,EP[6][0],q01); q23 = FMA2(bb,EP[6][1],q23); q45 = FMA2(bb,EP[6][2],q45);
        q6 = fmaf(p6,E6[6],q6);
        // times exp(emission)
        q01 = MUL2(q01, PK(x0,x1));
        q23 = MUL2(q23, PK(x2,x3));
        q45 = MUL2(q45, PK(x4,x5));
        q6 *= x6;
        // masked select
        p01 = M ? q01 : p01;
        p23 = M ? q23 : p23;
        p45 = M ? q45 : p45;
        p6  = M ? q6  : p6;
    };

#define RENORM() do { \
    float a0,a1,a2,a3,a4,a5; \
    UPK(p01,a0,a1); UPK(p23,a2,a3); UPK(p45,a4,a5); \
    float mx = fmaxf(fmaxf(fmaxf(a0,a1), fmaxf(a2,a3)), fmaxf(fmaxf(a4,a5), p6)); \
    int ex = (__float_as_int(mx) >> 23) & 0xFF; \
    float inv = __int_as_float((254 - ex) << 23); \
    xsum += ex - 127; \
    u64 iv = PK(inv, inv); \
    p01 = MUL2(p01,iv); p23 = MUL2(p23,iv); p45 = MUL2(p45,iv); p6 *= inv; } while (0)

#define PROC8(ROWP, LA, LB, MA, MB) do { \
    STEP(ROWP,0,(LA).x,(MA).x); STEP(ROWP,1,(LA).y,(MA).y); \
    STEP(ROWP,2,(LA).z,(MA).z); STEP(ROWP,3,(LA).w,(MA).w); \
    STEP(ROWP,4,(LB).x,(MB).x); STEP(ROWP,5,(LB).y,(MB).y); \
    STEP(ROWP,6,(LB).z,(MB).z); STEP(ROWP,7,(LB).w,(MB).w); \
    RENORM(); } while (0)

    // ---- prologue: stage macros 0..2 ----
    STAGE(0); STAGE(1); STAGE(2);

    int4 l0 = __ldg(lb4 + 0), l1 = __ldg(lb4 + 1);
    int4 m0 = __ldg(mb4 + 0), m1 = __ldg(mb4 + 1);

    CP_WAIT2(); __syncwarp();

    // ---- init (t=0) ----
    {
        float q[7];
#pragma unroll
        for (int j = 0; j < 7; j++) q[j] = __expf(__ldg(startT + j) + myrow0[j]);
        float mx = q[0];
#pragma unroll
        for (int j = 1; j < 7; j++) mx = fmaxf(mx, q[j]);
        int ex = (__float_as_int(mx) >> 23) & 0xFF;
        float inv = __int_as_float((254 - ex) << 23);
        xsum = ex - 127;
        p01 = PK(q[0]*inv, q[1]*inv);
        p23 = PK(q[2]*inv, q[3]*inv);
        p45 = PK(q[4]*inv, q[5]*inv);
        p6  = q[6]*inv;
        int L0 = l0.x < 0 ? 0 : l0.x;
        num = __ldg(startT + L0) + myrow0[L0];
        prev = L0;
    }

    // ---- macro 0: steps 1..7 ----
    STEP(myrow0,1,l0.y,m0.y); STEP(myrow0,2,l0.z,m0.z); STEP(myrow0,3,l0.w,m0.w);
    STEP(myrow0,4,l1.x,m1.x); STEP(myrow0,5,l1.y,m1.y);
    STEP(myrow0,6,l1.z,m1.z); STEP(myrow0,7,l1.w,m1.w);
    RENORM();
    __syncwarp();
    STAGE(3);

    // ---- mainloop: macros 1..63 ----
#pragma unroll 1
    for (int m = 1; m < 64; m++) {
        int4 la = __ldg(lb4 + 2*m),     lb = __ldg(lb4 + 2*m + 1);
        int4 ma = __ldg(mb4 + 2*m),     mb = __ldg(mb4 + 2*m + 1);
        CP_WAIT2(); __syncwarp();
        const float* rowp = (m % 3 == 0) ? myrow0 : (m % 3 == 1) ? myrow1 : myrow2;
        PROC8(rowp, la, lb, ma, mb);
        __syncwarp();
        if (m + 3 < 64) STAGE(m + 3);
    }

    // ---- finish ----
    float a0,a1,a2,a3,a4,a5;
    UPK(p01,a0,a1); UPK(p23,a2,a3); UPK(p45,a4,a5);
    float acc =        a0 * __expf(__ldg(endT + 0));
    acc = fmaf(a1, __expf(__ldg(endT + 1)), acc);
    acc = fmaf(a2, __expf(__ldg(endT + 2)), acc);
    acc = fmaf(a3, __expf(__ldg(endT + 3)), acc);
    acc = fmaf(a4, __expf(__ldg(endT + 4)), acc);
    acc = fmaf(a5, __expf(__ldg(endT + 5)), acc);
    acc = fmaf(p6, __expf(__ldg(endT + 6)), acc);
    float den  = __logf(acc) + (float)xsum * 0.69314718055994531f;
    float numf = num + __ldg(endT + prev);
    float r = den - numf;

#pragma unroll
    for (int off = 16; off > 0; off >>= 1)
        r += __shfl_xor_sync(0xFFFFFFFFu, r, off);
    if (lane == 0) atomicAdd(out, r);

#undef STAGE
#undef RENORM
#undef PROC8
}

extern "C" void kernel_launch(void* const* d_in, const int* in_sizes, int n_in,
                              void* d_out, int out_size)
{
    const float* em     = (const float*)d_in[0];
    const int*   labels = (const int*)  d_in[1];
    const int*   mask   = (const int*)  d_in[2];
    const float* startT = (const float*)d_in[3];
    const float* endT   = (const float*)d_in[4];
    const float* trans  = (const float*)d_in[5];

    cudaMemsetAsync(d_out, 0, sizeof(float));
    crf_fwd_kernel<<<128, 64>>>(em, labels, mask, startT, endT, trans, (float*)d_out);
}